// round 10
// baseline (speedup 1.0000x reference)
#include <cuda_runtime.h>
#include <cuda_bf16.h>

// ModernBertDecoderAttention: B=1, H=12, S=4096, D=64, fp32,
// causal + sliding_window=128.
// Outputs (tuple): attn_output [B,S,H,D], attn_weights [B,H,S,S].
//
// One block = 32 query rows of one head, 256 threads (8 warps), 4 q/warp.
// Warp processes its 4 queries jointly over the union key band (131 rows).
// After softmax, p is staged in smem (reusing the K buffer); the attn_weights
// rows are then written in ONE streaming float4 pass with the band merged in,
// and PV reads p via broadcast LDS.128 (no shuffles).

#define S_DIM 4096
#define H_DIM 12
#define D_DIM 64
#define SW    128
#define TQ    32
#define BAND  (TQ + SW - 1)   /* 159 */
#define UB    131             /* union band per warp: 128 + 3 */
#define KSTR  68              /* 68%32==4 -> conflict-free; 272B row, 16B aligned */
#define PQ    160             /* p slots per query (u = 0..159) */

__global__ __launch_bounds__(256, 4)
void mb_attn_kernel(const float* __restrict__ Q,
                    const float* __restrict__ K,
                    const float* __restrict__ V,
                    float* __restrict__ Out,   // [S,H,D] or nullptr
                    float* __restrict__ W)     // [H,S,S] or nullptr
{
    __shared__ __align__(16) float Ks[BAND * KSTR];   // 43,248 B (reused for p)

    const int blk  = blockIdx.x;               // h * (S/TQ) + tile
    const int h    = blk / (S_DIM / TQ);
    const int i0   = (blk % (S_DIM / TQ)) * TQ;
    const int tid  = threadIdx.x;
    const int lane = tid & 31;
    const int w    = tid >> 5;                 // warp 0..7
    const int qb   = w * 4;                    // first query of this warp in tile

    const int g0 = i0 - (SW - 1);              // global key row of smem row 0
    const int gq = g0 + qb;                    // global key row of union slot 0

    // ---- stage K band into smem (coalesced float4, zero-fill for g<0) ----
    {
        const float4* K4 = (const float4*)(K + (size_t)h * S_DIM * D_DIM);
        for (int idx = tid; idx < BAND * (D_DIM / 4); idx += 256) {
            const int row = idx >> 4;
            const int c4  = idx & 15;
            const int g   = g0 + row;
            float4 v = make_float4(0.f, 0.f, 0.f, 0.f);
            if (g >= 0) v = K4[(size_t)g * (D_DIM / 4) + c4];
            *(float4*)&Ks[row * KSTR + c4 * 4] = v;
        }
    }
    __syncthreads();

    // ---- QK: s[r][q] = q_q . k_(u=lane+32r), shared K loads across 4 q ----
    float s[5][4];
#pragma unroll
    for (int r = 0; r < 5; r++)
#pragma unroll
        for (int q = 0; q < 4; q++) s[r][q] = 0.f;

    {
        const float4* q4 =
            (const float4*)(Q + ((size_t)h * S_DIM + i0 + qb) * D_DIM);
#pragma unroll
        for (int d = 0; d < D_DIM / 4; d++) {
            const float4 q0 = __ldg(q4 + d);                    // broadcasts
            const float4 q1 = __ldg(q4 + 16 + d);
            const float4 q2 = __ldg(q4 + 32 + d);
            const float4 q3 = __ldg(q4 + 48 + d);
#pragma unroll
            for (int r = 0; r < 5; r++) {
                const int u   = lane + 32 * r;
                const int row = qb + ((u <= UB - 1) ? u : 0);   // clamp r=4 tail
                const float4 k = *(const float4*)&Ks[row * KSTR + 4 * d];
                s[r][0] = fmaf(q0.x, k.x, s[r][0]); s[r][0] = fmaf(q0.y, k.y, s[r][0]);
                s[r][0] = fmaf(q0.z, k.z, s[r][0]); s[r][0] = fmaf(q0.w, k.w, s[r][0]);
                s[r][1] = fmaf(q1.x, k.x, s[r][1]); s[r][1] = fmaf(q1.y, k.y, s[r][1]);
                s[r][1] = fmaf(q1.z, k.z, s[r][1]); s[r][1] = fmaf(q1.w, k.w, s[r][1]);
                s[r][2] = fmaf(q2.x, k.x, s[r][2]); s[r][2] = fmaf(q2.y, k.y, s[r][2]);
                s[r][2] = fmaf(q2.z, k.z, s[r][2]); s[r][2] = fmaf(q2.w, k.w, s[r][2]);
                s[r][3] = fmaf(q3.x, k.x, s[r][3]); s[r][3] = fmaf(q3.y, k.y, s[r][3]);
                s[r][3] = fmaf(q3.z, k.z, s[r][3]); s[r][3] = fmaf(q3.w, k.w, s[r][3]);
            }
        }
    }

    // ---- mask + softmax per query (warp shuffles); s becomes p ----
#pragma unroll
    for (int q = 0; q < 4; q++) {
        float mv = -1e30f;
#pragma unroll
        for (int r = 0; r < 5; r++) {
            const int u  = lane + 32 * r;
            const int tp = u - q;                       // band position
            const bool valid = (tp >= 0) && (tp <= 127) && (gq + u >= 0);
            const float sv = valid ? s[r][q] * 0.125f : -1e30f;
            s[r][q] = sv;
            mv = fmaxf(mv, sv);
        }
#pragma unroll
        for (int off = 16; off > 0; off >>= 1)
            mv = fmaxf(mv, __shfl_xor_sync(0xffffffffu, mv, off));
        float sum = 0.f;
#pragma unroll
        for (int r = 0; r < 5; r++) {
            const float e = __expf(s[r][q] - mv);       // ==0 for masked slots
            s[r][q] = e;
            sum += e;
        }
#pragma unroll
        for (int off = 16; off > 0; off >>= 1)
            sum += __shfl_xor_sync(0xffffffffu, sum, off);
        const float inv = 1.0f / sum;
#pragma unroll
        for (int r = 0; r < 5; r++) s[r][q] *= inv;
    }

    // ---- stage p into smem (reuse Ks; all QK reads are done) ----
    __syncthreads();                            // everyone finished reading Ks
    {
        float* pw = &Ks[w * (4 * PQ)];
#pragma unroll
        for (int q = 0; q < 4; q++)
#pragma unroll
            for (int r = 0; r < 5; r++)
                pw[q * PQ + lane + 32 * r] = s[r][q];   // masked slots are 0
    }
    // warp-private region: written and read by the same warp only

    // ---- attn_weights: ONE streaming pass per row, band merged in ----
    if (W) {
#pragma unroll
        for (int q = 0; q < 4; q++) {
            const int i  = i0 + qb + q;
            const int lo = (i > 127) ? (i - 127) : 0;
            const int hi = i;
            const float* pp = &Ks[w * (4 * PQ) + q * PQ];
            float4* wr4 = (float4*)(W + ((size_t)h * S_DIM + i) * S_DIM);
#pragma unroll 4
            for (int k = 0; k < 32; k++) {
                const int c4  = k * 32 + lane;
                const int col = 4 * c4;
                float4 v = make_float4(0.f, 0.f, 0.f, 0.f);
                if (col + 3 >= lo && col <= hi) {       // chunk intersects band
                    const int ub = col - gq;            // may be as low as -3
                    const int u0 = (ub     < 0) ? 0 : ub;
                    const int u1 = (ub + 1 < 0) ? 0 : ub + 1;
                    const int u2 = (ub + 2 < 0) ? 0 : ub + 2;
                    const int u3 = (ub + 3 < 0) ? 0 : ub + 3;
                    v.x = (col     >= lo && col     <= hi) ? pp[u0] : 0.f;
                    v.y = (col + 1 >= lo && col + 1 <= hi) ? pp[u1] : 0.f;
                    v.z = (col + 2 >= lo && col + 2 <= hi) ? pp[u2] : 0.f;
                    v.w = (col + 3 >= lo && col + 3 <= hi) ? pp[u3] : 0.f;
                }
                wr4[c4] = v;
            }
        }
    }

    // ---- PV: one pass over union band; p via broadcast LDS.128 ----
    if (Out) {
        float2 acc0 = make_float2(0.f, 0.f);
        float2 acc1 = make_float2(0.f, 0.f);
        float2 acc2 = make_float2(0.f, 0.f);
        float2 acc3 = make_float2(0.f, 0.f);
        const float*  vb = V + (size_t)h * S_DIM * D_DIM + 2 * lane;
        const float4* pb = (const float4*)&Ks[w * (4 * PQ)];
#pragma unroll
        for (int tb = 0; tb < 33; tb++) {               // t = 4*tb + e, 0..131
            const float4 p0 = pb[tb];                   // q=0
            const float4 p1 = pb[(PQ / 4)     + tb];    // q=1
            const float4 p2 = pb[(PQ / 4) * 2 + tb];    // q=2
            const float4 p3 = pb[(PQ / 4) * 3 + tb];    // q=3
#pragma unroll
            for (int e = 0; e < 4; e++) {
                int j = gq + 4 * tb + e;
                if (j < 0) j = 0;                       // p==0 there
                if (j > S_DIM - 1) j = S_DIM - 1;       // p==0 there (t=131 tail)
                const float2 vv = *(const float2*)&vb[(size_t)j * D_DIM];
                const float q0 = (e == 0) ? p0.x : (e == 1) ? p0.y : (e == 2) ? p0.z : p0.w;
                const float q1 = (e == 0) ? p1.x : (e == 1) ? p1.y : (e == 2) ? p1.z : p1.w;
                const float q2 = (e == 0) ? p2.x : (e == 1) ? p2.y : (e == 2) ? p2.z : p2.w;
                const float q3 = (e == 0) ? p3.x : (e == 1) ? p3.y : (e == 2) ? p3.z : p3.w;
                acc0.x = fmaf(q0, vv.x, acc0.x); acc0.y = fmaf(q0, vv.y, acc0.y);
                acc1.x = fmaf(q1, vv.x, acc1.x); acc1.y = fmaf(q1, vv.y, acc1.y);
                acc2.x = fmaf(q2, vv.x, acc2.x); acc2.y = fmaf(q2, vv.y, acc2.y);
                acc3.x = fmaf(q3, vv.x, acc3.x); acc3.y = fmaf(q3, vv.y, acc3.y);
            }
        }
        const int ib = i0 + qb;
        *(float2*)&Out[((size_t)(ib    ) * H_DIM + h) * D_DIM + 2 * lane] = acc0;
        *(float2*)&Out[((size_t)(ib + 1) * H_DIM + h) * D_DIM + 2 * lane] = acc1;
        *(float2*)&Out[((size_t)(ib + 2) * H_DIM + h) * D_DIM + 2 * lane] = acc2;
        *(float2*)&Out[((size_t)(ib + 3) * H_DIM + h) * D_DIM + 2 * lane] = acc3;
    }
}

extern "C" void kernel_launch(void* const* d_in, const int* in_sizes, int n_in,
                              void* d_out, int out_size)
{
    const float* Q = (const float*)d_in[0];
    const float* K = (const float*)d_in[1];
    const float* V = (const float*)d_in[2];
    // d_in[3] = attention_mask (all-ones, unused)
    // d_in[4] = sliding_window = 128 (hardcoded)

    const long long OUT_ELEMS = (long long)S_DIM * H_DIM * D_DIM;   // 3,145,728
    const long long W_ELEMS   = (long long)H_DIM * S_DIM * S_DIM;   // 201,326,592

    float* out = nullptr;
    float* w   = nullptr;
    const long long osz = (long long)out_size;
    if (osz == OUT_ELEMS) {
        out = (float*)d_out;
    } else if (osz == W_ELEMS) {
        w = (float*)d_out;
    } else {
        out = (float*)d_out;                 // tuple order: output, weights
        w   = (float*)d_out + OUT_ELEMS;
    }

    dim3 grid(H_DIM * (S_DIM / TQ));         // 1536 blocks
    dim3 block(256);
    mb_attn_kernel<<<grid, block>>>(Q, K, V, out, w);
}

// round 11
// speedup vs baseline: 1.0367x; 1.0367x over previous
#include <cuda_runtime.h>
#include <cuda_bf16.h>

// ModernBertDecoderAttention: B=1, H=12, S=4096, D=64, fp32,
// causal + sliding_window=128.
// Outputs (tuple): attn_output [B,S,H,D], attn_weights [B,H,S,S].
//
// R9 structure (best: 166us) + occupancy 4->5 blocks/SM via launch_bounds.
// One block = 32 query rows of one head, 256 threads (8 warps), 4 q/warp.
// Warp processes its 4 queries JOINTLY over the union key band (131 rows):
//  - QK: lane owns union rows u=lane+32r (r=0..4); each K load feeds 4 queries.
//  - PV: single pass over union rows; each V row loaded once, shared by 4 queries.

#define S_DIM 4096
#define H_DIM 12
#define D_DIM 64
#define SW    128
#define TQ    32
#define BAND  (TQ + SW - 1)   /* 159 */
#define UB    131             /* union band per warp: 128 + 3 */
#define KSTR  68              /* 68%32==4 -> conflict-free; 272B row, 16B aligned */

__global__ __launch_bounds__(256, 5)
void mb_attn_kernel(const float* __restrict__ Q,
                    const float* __restrict__ K,
                    const float* __restrict__ V,
                    float* __restrict__ Out,   // [S,H,D] or nullptr
                    float* __restrict__ W)     // [H,S,S] or nullptr
{
    __shared__ float Ks[BAND * KSTR];          // 43,248 B

    const int blk  = blockIdx.x;               // h * (S/TQ) + tile
    const int h    = blk / (S_DIM / TQ);
    const int i0   = (blk % (S_DIM / TQ)) * TQ;
    const int tid  = threadIdx.x;
    const int lane = tid & 31;
    const int w    = tid >> 5;                 // warp 0..7
    const int qb   = w * 4;                    // first query of this warp in tile

    const int g0 = i0 - (SW - 1);              // global key row of smem row 0

    // ---- stage K band into smem (coalesced float4, zero-fill for g<0) ----
    {
        const float4* K4 = (const float4*)(K + (size_t)h * S_DIM * D_DIM);
        for (int idx = tid; idx < BAND * (D_DIM / 4); idx += 256) {
            const int row = idx >> 4;
            const int c4  = idx & 15;
            const int g   = g0 + row;
            float4 v = make_float4(0.f, 0.f, 0.f, 0.f);
            if (g >= 0) v = K4[(size_t)g * (D_DIM / 4) + c4];
            *(float4*)&Ks[row * KSTR + c4 * 4] = v;
        }
    }
    __syncthreads();

    // ---- QK: s[r][q] = q_q . k_(u=lane+32r), shared K loads across 4 q ----
    float s[5][4];
#pragma unroll
    for (int r = 0; r < 5; r++)
#pragma unroll
        for (int q = 0; q < 4; q++) s[r][q] = 0.f;

    {
        const float4* q4 =
            (const float4*)(Q + ((size_t)h * S_DIM + i0 + qb) * D_DIM);
#pragma unroll
        for (int d = 0; d < D_DIM / 4; d++) {
            const float4 q0 = __ldg(q4 + d);                    // broadcasts
            const float4 q1 = __ldg(q4 + 16 + d);
            const float4 q2 = __ldg(q4 + 32 + d);
            const float4 q3 = __ldg(q4 + 48 + d);
#pragma unroll
            for (int r = 0; r < 5; r++) {
                const int u   = lane + 32 * r;
                const int row = qb + ((u <= UB - 1) ? u : 0);   // clamp r=4 tail
                const float4 k = *(const float4*)&Ks[row * KSTR + 4 * d];
                s[r][0] = fmaf(q0.x, k.x, s[r][0]); s[r][0] = fmaf(q0.y, k.y, s[r][0]);
                s[r][0] = fmaf(q0.z, k.z, s[r][0]); s[r][0] = fmaf(q0.w, k.w, s[r][0]);
                s[r][1] = fmaf(q1.x, k.x, s[r][1]); s[r][1] = fmaf(q1.y, k.y, s[r][1]);
                s[r][1] = fmaf(q1.z, k.z, s[r][1]); s[r][1] = fmaf(q1.w, k.w, s[r][1]);
                s[r][2] = fmaf(q2.x, k.x, s[r][2]); s[r][2] = fmaf(q2.y, k.y, s[r][2]);
                s[r][2] = fmaf(q2.z, k.z, s[r][2]); s[r][2] = fmaf(q2.w, k.w, s[r][2]);
                s[r][3] = fmaf(q3.x, k.x, s[r][3]); s[r][3] = fmaf(q3.y, k.y, s[r][3]);
                s[r][3] = fmaf(q3.z, k.z, s[r][3]); s[r][3] = fmaf(q3.w, k.w, s[r][3]);
            }
        }
    }

    // ---- mask + softmax per query (warp shuffles); s becomes p ----
#pragma unroll
    for (int q = 0; q < 4; q++) {
        float mv = -1e30f;
#pragma unroll
        for (int r = 0; r < 5; r++) {
            const int u  = lane + 32 * r;
            const int tp = u - q;                       // band position
            const bool valid = (tp >= 0) && (tp <= 127) && (g0 + qb + u >= 0);
            const float sv = valid ? s[r][q] * 0.125f : -1e30f;
            s[r][q] = sv;
            mv = fmaxf(mv, sv);
        }
#pragma unroll
        for (int off = 16; off > 0; off >>= 1)
            mv = fmaxf(mv, __shfl_xor_sync(0xffffffffu, mv, off));
        float sum = 0.f;
#pragma unroll
        for (int r = 0; r < 5; r++) {
            const float e = __expf(s[r][q] - mv);       // ==0 for masked slots
            s[r][q] = e;
            sum += e;
        }
#pragma unroll
        for (int off = 16; off > 0; off >>= 1)
            sum += __shfl_xor_sync(0xffffffffu, sum, off);
        const float inv = 1.0f / sum;
#pragma unroll
        for (int r = 0; r < 5; r++) s[r][q] *= inv;
    }

    // ---- attn_weights: per-query zero-fill + scattered band overwrite ----
    if (W) {
#pragma unroll
        for (int q = 0; q < 4; q++) {
            const int i = i0 + qb + q;
            float*  wrow = W + ((size_t)h * S_DIM + i) * S_DIM;
            float4* wr4  = (float4*)wrow;
            const float4 z = make_float4(0.f, 0.f, 0.f, 0.f);
#pragma unroll
            for (int k = 0; k < (S_DIM / 4) / 32; k++)   // 32 iterations
                wr4[k * 32 + lane] = z;
            __syncwarp();                                 // zeros before band
#pragma unroll
            for (int r = 0; r < 5; r++) {
                const int u  = lane + 32 * r;
                const int tp = u - q;
                const int j  = g0 + qb + u;
                if (tp >= 0 && tp <= 127 && j >= 0) wrow[j] = s[r][q];
            }
        }
    }

    // ---- PV: one pass over the union band; V row shared by 4 queries ----
    if (Out) {
        float2 acc[4];
#pragma unroll
        for (int q = 0; q < 4; q++) acc[q] = make_float2(0.f, 0.f);

        const float* vbase = V + (size_t)h * S_DIM * D_DIM + 2 * lane;
#pragma unroll
        for (int t = 0; t < UB; t++) {
            int j = g0 + qb + t;
            const int jc = (j < 0) ? 0 : j;              // masked -> p==0, safe
            const float2 v = *(const float2*)&vbase[(size_t)jc * D_DIM];
            const int r  = t >> 5;                       // literal (unrolled)
            const int ln = t & 31;
#pragma unroll
            for (int q = 0; q < 4; q++) {
                const int tp = t - q;
                if (tp >= 0 && tp <= 127) {              // compile-time prune
                    const float pq = __shfl_sync(0xffffffffu, s[r][q], ln);
                    acc[q].x = fmaf(pq, v.x, acc[q].x);
                    acc[q].y = fmaf(pq, v.y, acc[q].y);
                }
            }
        }
#pragma unroll
        for (int q = 0; q < 4; q++) {
            const int i = i0 + qb + q;
            *(float2*)&Out[((size_t)i * H_DIM + h) * D_DIM + 2 * lane] = acc[q];
        }
    }
}

extern "C" void kernel_launch(void* const* d_in, const int* in_sizes, int n_in,
                              void* d_out, int out_size)
{
    const float* Q = (const float*)d_in[0];
    const float* K = (const float*)d_in[1];
    const float* V = (const float*)d_in[2];
    // d_in[3] = attention_mask (all-ones, unused)
    // d_in[4] = sliding_window = 128 (hardcoded)

    const long long OUT_ELEMS = (long long)S_DIM * H_DIM * D_DIM;   // 3,145,728
    const long long W_ELEMS   = (long long)H_DIM * S_DIM * S_DIM;   // 201,326,592

    float* out = nullptr;
    float* w   = nullptr;
    const long long osz = (long long)out_size;
    if (osz == OUT_ELEMS) {
        out = (float*)d_out;
    } else if (osz == W_ELEMS) {
        w = (float*)d_out;
    } else {
        out = (float*)d_out;                 // tuple order: output, weights
        w   = (float*)d_out + OUT_ELEMS;
    }

    dim3 grid(H_DIM * (S_DIM / TQ));         // 1536 blocks
    dim3 block(256);
    mb_attn_kernel<<<grid, block>>>(Q, K, V, out, w);
}

// round 12
// speedup vs baseline: 1.0873x; 1.0488x over previous
#include <cuda_runtime.h>
#include <cuda_bf16.h>

// ModernBertDecoderAttention: B=1, H=12, S=4096, D=64, fp32,
// causal + sliding_window=128.
// Outputs (tuple): attn_output [B,S,H,D], attn_weights [B,H,S,S].
//
// Grid-specialized single launch (3072 blocks):
//   odd blocks  -> pure streaming zero-fill of each row's OUT-OF-BAND float4
//                  chunks (memset-style, no smem/barriers).
//   even blocks -> R9 compute (union-band QK + softmax + PV) writing ONLY the
//                  <=33 in-band float4 chunks per row (p staged in smem,
//                  shift-aligned so chunks load with one LDS.128) plus Out.
// Band / out-of-band chunks are exact complements -> no ordering needed.

#define S_DIM 4096
#define H_DIM 12
#define D_DIM 64
#define SW    128
#define TQ    32
#define BAND  (TQ + SW - 1)   /* 159 */
#define UB    131             /* union band per warp: 128 + 3 */
#define KSTR  68              /* 68%32==4 -> conflict-free; 272B row, 16B aligned */
#define PQP   168             /* padded p slots per query (shift<=3, u<=159) */

__global__ __launch_bounds__(256, 4)
void mb_attn_kernel(const float* __restrict__ Q,
                    const float* __restrict__ K,
                    const float* __restrict__ V,
                    float* __restrict__ Out,   // [S,H,D] or nullptr
                    float* __restrict__ W)     // [H,S,S] or nullptr
{
    __shared__ __align__(16) float Ks[BAND * KSTR];   // 43,248 B (p aliases front)

    const int role = blockIdx.x & 1;
    const int idx  = blockIdx.x >> 1;           // 0..1535
    const int h    = idx / (S_DIM / TQ);
    const int i0   = (idx % (S_DIM / TQ)) * TQ;
    const int tid  = threadIdx.x;

    // ================= zero-fill blocks (odd) =================
    if (role) {
        if (!W) return;
        float4* base = (float4*)(W + ((size_t)h * S_DIM + i0) * S_DIM);
        const float4 z = make_float4(0.f, 0.f, 0.f, 0.f);
#pragma unroll 4
        for (int r = 0; r < TQ; r++) {
            const int i  = i0 + r;
            const int c0 = ((i > 127) ? (i - 127) : 0) >> 2;
            const int c1 = i >> 2;
            float4* row4 = base + (size_t)r * (S_DIM / 4);
            for (int c = tid; c < c0; c += 256)            // prefix chunks
                row4[c] = z;
            for (int c = c1 + 1 + tid; c < S_DIM / 4; c += 256)  // suffix
                row4[c] = z;
        }
        return;
    }

    // ================= compute blocks (even) =================
    const int lane = tid & 31;
    const int w    = tid >> 5;                 // warp 0..7
    const int qb   = w * 4;                    // first query of this warp
    const int g0 = i0 - (SW - 1);              // global key row of smem row 0
    const int gq = g0 + qb;                    // global key row of union slot 0

    // ---- stage K band into smem (coalesced float4, zero-fill for g<0) ----
    {
        const float4* K4 = (const float4*)(K + (size_t)h * S_DIM * D_DIM);
        for (int t = tid; t < BAND * (D_DIM / 4); t += 256) {
            const int row = t >> 4;
            const int c4  = t & 15;
            const int g   = g0 + row;
            float4 v = make_float4(0.f, 0.f, 0.f, 0.f);
            if (g >= 0) v = K4[(size_t)g * (D_DIM / 4) + c4];
            *(float4*)&Ks[row * KSTR + c4 * 4] = v;
        }
    }
    __syncthreads();

    // ---- QK: s[r][q] = q_q . k_(u=lane+32r), shared K loads across 4 q ----
    float s[5][4];
#pragma unroll
    for (int r = 0; r < 5; r++)
#pragma unroll
        for (int q = 0; q < 4; q++) s[r][q] = 0.f;

    {
        const float4* q4 =
            (const float4*)(Q + ((size_t)h * S_DIM + i0 + qb) * D_DIM);
#pragma unroll
        for (int d = 0; d < D_DIM / 4; d++) {
            const float4 q0 = __ldg(q4 + d);                    // broadcasts
            const float4 q1 = __ldg(q4 + 16 + d);
            const float4 q2 = __ldg(q4 + 32 + d);
            const float4 q3 = __ldg(q4 + 48 + d);
#pragma unroll
            for (int r = 0; r < 5; r++) {
                const int u   = lane + 32 * r;
                const int row = qb + ((u <= UB - 1) ? u : 0);   // clamp r=4 tail
                const float4 k = *(const float4*)&Ks[row * KSTR + 4 * d];
                s[r][0] = fmaf(q0.x, k.x, s[r][0]); s[r][0] = fmaf(q0.y, k.y, s[r][0]);
                s[r][0] = fmaf(q0.z, k.z, s[r][0]); s[r][0] = fmaf(q0.w, k.w, s[r][0]);
                s[r][1] = fmaf(q1.x, k.x, s[r][1]); s[r][1] = fmaf(q1.y, k.y, s[r][1]);
                s[r][1] = fmaf(q1.z, k.z, s[r][1]); s[r][1] = fmaf(q1.w, k.w, s[r][1]);
                s[r][2] = fmaf(q2.x, k.x, s[r][2]); s[r][2] = fmaf(q2.y, k.y, s[r][2]);
                s[r][2] = fmaf(q2.z, k.z, s[r][2]); s[r][2] = fmaf(q2.w, k.w, s[r][2]);
                s[r][3] = fmaf(q3.x, k.x, s[r][3]); s[r][3] = fmaf(q3.y, k.y, s[r][3]);
                s[r][3] = fmaf(q3.z, k.z, s[r][3]); s[r][3] = fmaf(q3.w, k.w, s[r][3]);
            }
        }
    }

    // ---- mask + softmax per query (warp shuffles); s becomes p ----
#pragma unroll
    for (int q = 0; q < 4; q++) {
        float mv = -1e30f;
#pragma unroll
        for (int r = 0; r < 5; r++) {
            const int u  = lane + 32 * r;
            const int tp = u - q;                       // band position
            const bool valid = (tp >= 0) && (tp <= 127) && (gq + u >= 0);
            const float sv = valid ? s[r][q] * 0.125f : -1e30f;
            s[r][q] = sv;
            mv = fmaxf(mv, sv);
        }
#pragma unroll
        for (int off = 16; off > 0; off >>= 1)
            mv = fmaxf(mv, __shfl_xor_sync(0xffffffffu, mv, off));
        float sum = 0.f;
#pragma unroll
        for (int r = 0; r < 5; r++) {
            const float e = __expf(s[r][q] - mv);       // ==0 for masked slots
            s[r][q] = e;
            sum += e;
        }
#pragma unroll
        for (int off = 16; off > 0; off >>= 1)
            sum += __shfl_xor_sync(0xffffffffu, sum, off);
        const float inv = 1.0f / sum;
#pragma unroll
        for (int r = 0; r < 5; r++) s[r][q] *= inv;
    }

    // ---- W band write: stage p in smem (shift-aligned), write <=33 chunks/row ----
    if (W) {
        __syncthreads();                        // all QK reads of Ks done
        float* pw = &Ks[w * (4 * PQP)];         // warp-private region
        {   // zero the padded region (covers shift head/tail + u>159)
            float4* pz = (float4*)pw;
#pragma unroll
            for (int k = lane; k < PQP; k += 32)        // 168 float4
                pz[k] = make_float4(0.f, 0.f, 0.f, 0.f);
        }
        __syncwarp();
        const int sh = gq & 3;                  // alignment shift (0..3)
#pragma unroll
        for (int q = 0; q < 4; q++)
#pragma unroll
            for (int r = 0; r < 5; r++)
                pw[q * PQP + sh + lane + 32 * r] = s[r][q];   // masked -> 0
        __syncwarp();

        const int obase = (gq - sh) >> 2;       // aligned base chunk (may be <0)
#pragma unroll
        for (int q = 0; q < 4; q++) {
            const int i  = i0 + qb + q;
            const int c0 = ((i > 127) ? (i - 127) : 0) >> 2;
            const int c1 = i >> 2;
            float4* wr4 = (float4*)(W + ((size_t)h * S_DIM + i) * S_DIM);
            const float4* pp4 = (const float4*)&pw[q * PQP];
            int c = c0 + lane;
            if (c <= c1) wr4[c] = pp4[c - obase];
            c += 32;
            if (c <= c1) wr4[c] = pp4[c - obase];
        }
    }

    // ---- PV: one pass over the union band; V row shared by 4 queries ----
    if (Out) {
        float2 acc[4];
#pragma unroll
        for (int q = 0; q < 4; q++) acc[q] = make_float2(0.f, 0.f);

        const float* vbase = V + (size_t)h * S_DIM * D_DIM + 2 * lane;
#pragma unroll
        for (int t = 0; t < UB; t++) {
            int j = gq + t;
            const int jc = (j < 0) ? 0 : j;              // masked -> p==0, safe
            const float2 v = *(const float2*)&vbase[(size_t)jc * D_DIM];
            const int r  = t >> 5;                       // literal (unrolled)
            const int ln = t & 31;
#pragma unroll
            for (int q = 0; q < 4; q++) {
                const int tp = t - q;
                if (tp >= 0 && tp <= 127) {              // compile-time prune
                    const float pq = __shfl_sync(0xffffffffu, s[r][q], ln);
                    acc[q].x = fmaf(pq, v.x, acc[q].x);
                    acc[q].y = fmaf(pq, v.y, acc[q].y);
                }
            }
        }
#pragma unroll
        for (int q = 0; q < 4; q++) {
            const int i = i0 + qb + q;
            *(float2*)&Out[((size_t)i * H_DIM + h) * D_DIM + 2 * lane] = acc[q];
        }
    }
}

extern "C" void kernel_launch(void* const* d_in, const int* in_sizes, int n_in,
                              void* d_out, int out_size)
{
    const float* Q = (const float*)d_in[0];
    const float* K = (const float*)d_in[1];
    const float* V = (const float*)d_in[2];
    // d_in[3] = attention_mask (all-ones, unused)
    // d_in[4] = sliding_window = 128 (hardcoded)

    const long long OUT_ELEMS = (long long)S_DIM * H_DIM * D_DIM;   // 3,145,728
    const long long W_ELEMS   = (long long)H_DIM * S_DIM * S_DIM;   // 201,326,592

    float* out = nullptr;
    float* w   = nullptr;
    const long long osz = (long long)out_size;
    if (osz == OUT_ELEMS) {
        out = (float*)d_out;
    } else if (osz == W_ELEMS) {
        w = (float*)d_out;
    } else {
        out = (float*)d_out;                 // tuple order: output, weights
        w   = (float*)d_out + OUT_ELEMS;
    }

    dim3 grid(2 * H_DIM * (S_DIM / TQ));     // 3072 blocks (parity-specialized)
    dim3 block(256);
    mb_attn_kernel<<<grid, block>>>(Q, K, V, out, w);
}

// round 13
// speedup vs baseline: 1.1176x; 1.0279x over previous
#include <cuda_runtime.h>
#include <cuda_bf16.h>

// ModernBertDecoderAttention: B=1, H=12, S=4096, D=64, fp32,
// causal + sliding_window=128.
// Outputs (tuple): attn_output [B,S,H,D], attn_weights [B,H,S,S].
//
// Grid-specialized single launch (3072 blocks):
//   odd blocks  -> pure streaming zero-fill of out-of-band W chunks (__stcs).
//   even blocks -> union-band QK + softmax; p staged shift-aligned in smem,
//                  reused for BOTH the W band-chunk writes (<=33 float4/row,
//                  __stcs) and the PV pass (aligned LDS.128, no shuffles).
// Band / out-of-band chunks are exact complements -> each W element written once.

#define S_DIM 4096
#define H_DIM 12
#define D_DIM 64
#define SW    128
#define TQ    32
#define BAND  (TQ + SW - 1)   /* 159 */
#define UB    131             /* union band per warp: 128 + 3 */
#define KSTR  68              /* 68%32==4 -> conflict-free; 272B row, 16B aligned */
#define PQP   168             /* padded p slots per query (mult of 4; sh+159 < 168) */

__global__ __launch_bounds__(256, 4)
void mb_attn_kernel(const float* __restrict__ Q,
                    const float* __restrict__ K,
                    const float* __restrict__ V,
                    float* __restrict__ Out,   // [S,H,D] or nullptr
                    float* __restrict__ W)     // [H,S,S] or nullptr
{
    __shared__ __align__(16) float Ks[BAND * KSTR];   // 43,248 B (p aliases front)

    const int role = blockIdx.x & 1;
    const int idx  = blockIdx.x >> 1;           // 0..1535
    const int h    = idx / (S_DIM / TQ);
    const int i0   = (idx % (S_DIM / TQ)) * TQ;
    const int tid  = threadIdx.x;

    // ================= zero-fill blocks (odd) =================
    if (role) {
        if (!W) return;
        float4* base = (float4*)(W + ((size_t)h * S_DIM + i0) * S_DIM);
        const float4 z = make_float4(0.f, 0.f, 0.f, 0.f);
#pragma unroll 4
        for (int r = 0; r < TQ; r++) {
            const int i  = i0 + r;
            const int c0 = ((i > 127) ? (i - 127) : 0) >> 2;
            const int c1 = i >> 2;
            float4* row4 = base + (size_t)r * (S_DIM / 4);
            for (int c = tid; c < c0; c += 256)                 // prefix chunks
                __stcs(&row4[c], z);
            for (int c = c1 + 1 + tid; c < S_DIM / 4; c += 256) // suffix chunks
                __stcs(&row4[c], z);
        }
        return;
    }

    // ================= compute blocks (even) =================
    const int lane = tid & 31;
    const int w    = tid >> 5;                 // warp 0..7
    const int qb   = w * 4;                    // first query of this warp
    const int g0 = i0 - (SW - 1);              // global key row of smem row 0
    const int gq = g0 + qb;                    // global key row of union slot 0
    const int sh = gq & 3;                     // alignment shift (0..3)
    const int ga = gq - sh;                    // 4-aligned base key row

    // ---- stage K band into smem (coalesced float4, zero-fill for g<0) ----
    {
        const float4* K4 = (const float4*)(K + (size_t)h * S_DIM * D_DIM);
        for (int t = tid; t < BAND * (D_DIM / 4); t += 256) {
            const int row = t >> 4;
            const int c4  = t & 15;
            const int g   = g0 + row;
            float4 v = make_float4(0.f, 0.f, 0.f, 0.f);
            if (g >= 0) v = K4[(size_t)g * (D_DIM / 4) + c4];
            *(float4*)&Ks[row * KSTR + c4 * 4] = v;
        }
    }
    __syncthreads();

    // ---- QK: s[r][q] = q_q . k_(u=lane+32r), shared K loads across 4 q ----
    float s[5][4];
#pragma unroll
    for (int r = 0; r < 5; r++)
#pragma unroll
        for (int q = 0; q < 4; q++) s[r][q] = 0.f;

    {
        const float4* q4 =
            (const float4*)(Q + ((size_t)h * S_DIM + i0 + qb) * D_DIM);
#pragma unroll
        for (int d = 0; d < D_DIM / 4; d++) {
            const float4 q0 = __ldg(q4 + d);                    // broadcasts
            const float4 q1 = __ldg(q4 + 16 + d);
            const float4 q2 = __ldg(q4 + 32 + d);
            const float4 q3 = __ldg(q4 + 48 + d);
#pragma unroll
            for (int r = 0; r < 5; r++) {
                const int u   = lane + 32 * r;
                const int row = qb + ((u <= UB - 1) ? u : 0);   // clamp r=4 tail
                const float4 k = *(const float4*)&Ks[row * KSTR + 4 * d];
                s[r][0] = fmaf(q0.x, k.x, s[r][0]); s[r][0] = fmaf(q0.y, k.y, s[r][0]);
                s[r][0] = fmaf(q0.z, k.z, s[r][0]); s[r][0] = fmaf(q0.w, k.w, s[r][0]);
                s[r][1] = fmaf(q1.x, k.x, s[r][1]); s[r][1] = fmaf(q1.y, k.y, s[r][1]);
                s[r][1] = fmaf(q1.z, k.z, s[r][1]); s[r][1] = fmaf(q1.w, k.w, s[r][1]);
                s[r][2] = fmaf(q2.x, k.x, s[r][2]); s[r][2] = fmaf(q2.y, k.y, s[r][2]);
                s[r][2] = fmaf(q2.z, k.z, s[r][2]); s[r][2] = fmaf(q2.w, k.w, s[r][2]);
                s[r][3] = fmaf(q3.x, k.x, s[r][3]); s[r][3] = fmaf(q3.y, k.y, s[r][3]);
                s[r][3] = fmaf(q3.z, k.z, s[r][3]); s[r][3] = fmaf(q3.w, k.w, s[r][3]);
            }
        }
    }

    // ---- mask + softmax per query (warp shuffles); s becomes p ----
#pragma unroll
    for (int q = 0; q < 4; q++) {
        float mv = -1e30f;
#pragma unroll
        for (int r = 0; r < 5; r++) {
            const int u  = lane + 32 * r;
            const int tp = u - q;                       // band position
            const bool valid = (tp >= 0) && (tp <= 127) && (gq + u >= 0);
            const float sv = valid ? s[r][q] * 0.125f : -1e30f;
            s[r][q] = sv;
            mv = fmaxf(mv, sv);
        }
#pragma unroll
        for (int off = 16; off > 0; off >>= 1)
            mv = fmaxf(mv, __shfl_xor_sync(0xffffffffu, mv, off));
        float sum = 0.f;
#pragma unroll
        for (int r = 0; r < 5; r++) {
            const float e = __expf(s[r][q] - mv);       // ==0 for masked slots
            s[r][q] = e;
            sum += e;
        }
#pragma unroll
        for (int off = 16; off > 0; off >>= 1)
            sum += __shfl_xor_sync(0xffffffffu, sum, off);
        const float inv = 1.0f / sum;
#pragma unroll
        for (int r = 0; r < 5; r++) s[r][q] *= inv;
    }

    // ---- stage p in smem, shift-aligned: pw[q*PQP + sh + u] = p(q,u) ----
    __syncthreads();                            // all QK reads of Ks done
    float* pw = &Ks[w * (4 * PQP)];             // warp-private region
    {
        float4* pz = (float4*)pw;
#pragma unroll
        for (int k = lane; k < PQP; k += 32)    // zero 168 float4 (full region)
            pz[k] = make_float4(0.f, 0.f, 0.f, 0.f);
    }
    __syncwarp();
#pragma unroll
    for (int q = 0; q < 4; q++)
#pragma unroll
        for (int r = 0; r < 5; r++)
            pw[q * PQP + sh + lane + 32 * r] = s[r][q];   // masked -> 0
    __syncwarp();

    // ---- W band write: <=33 aligned float4 chunks per row (__stcs) ----
    if (W) {
        const int obase = ga >> 2;              // aligned base chunk (may be <0)
#pragma unroll
        for (int q = 0; q < 4; q++) {
            const int i  = i0 + qb + q;
            const int c0 = ((i > 127) ? (i - 127) : 0) >> 2;
            const int c1 = i >> 2;
            float4* wr4 = (float4*)(W + ((size_t)h * S_DIM + i) * S_DIM);
            const float4* pp4 = (const float4*)&pw[q * PQP];
            int c = c0 + lane;
            if (c <= c1) __stcs(&wr4[c], pp4[c - obase]);
            c += 32;
            if (c <= c1) __stcs(&wr4[c], pp4[c - obase]);
        }
    }

    // ---- PV: p via aligned LDS.128; V row shared by 4 queries ----
    if (Out) {
        float2 acc0 = make_float2(0.f, 0.f);
        float2 acc1 = make_float2(0.f, 0.f);
        float2 acc2 = make_float2(0.f, 0.f);
        float2 acc3 = make_float2(0.f, 0.f);
        const float*  vb = V + (size_t)h * S_DIM * D_DIM + 2 * lane;
        const float4* pb = (const float4*)pw;
        // x = 4*xb + e indexes staged p; key row j = ga + x; p==0 for x<sh
        // and for x>sh+130, so 34 chunks cover everything.
#pragma unroll
        for (int xb = 0; xb < 34; xb++) {
            const float4 p0 = pb[xb];                    // q=0
            const float4 p1 = pb[(PQP / 4)     + xb];    // q=1
            const float4 p2 = pb[(PQP / 4) * 2 + xb];    // q=2
            const float4 p3 = pb[(PQP / 4) * 3 + xb];    // q=3
#pragma unroll
            for (int e = 0; e < 4; e++) {
                int j = ga + 4 * xb + e;
                if (j < 0) j = 0;                        // p==0 there
                if (j > S_DIM - 1) j = S_DIM - 1;        // p==0 there
                const float2 vv = *(const float2*)&vb[(size_t)j * D_DIM];
                const float f0 = (e == 0) ? p0.x : (e == 1) ? p0.y : (e == 2) ? p0.z : p0.w;
                const float f1 = (e == 0) ? p1.x : (e == 1) ? p1.y : (e == 2) ? p1.z : p1.w;
                const float f2 = (e == 0) ? p2.x : (e == 1) ? p2.y : (e == 2) ? p2.z : p2.w;
                const float f3 = (e == 0) ? p3.x : (e == 1) ? p3.y : (e == 2) ? p3.z : p3.w;
                acc0.x = fmaf(f0, vv.x, acc0.x); acc0.y = fmaf(f0, vv.y, acc0.y);
                acc1.x = fmaf(f1, vv.x, acc1.x); acc1.y = fmaf(f1, vv.y, acc1.y);
                acc2.x = fmaf(f2, vv.x, acc2.x); acc2.y = fmaf(f2, vv.y, acc2.y);
                acc3.x = fmaf(f3, vv.x, acc3.x); acc3.y = fmaf(f3, vv.y, acc3.y);
            }
        }
        const int ib = i0 + qb;
        __stcs((float2*)&Out[((size_t)(ib    ) * H_DIM + h) * D_DIM + 2 * lane], acc0);
        __stcs((float2*)&Out[((size_t)(ib + 1) * H_DIM + h) * D_DIM + 2 * lane], acc1);
        __stcs((float2*)&Out[((size_t)(ib + 2) * H_DIM + h) * D_DIM + 2 * lane], acc2);
        __stcs((float2*)&Out[((size_t)(ib + 3) * H_DIM + h) * D_DIM + 2 * lane], acc3);
    }
}

extern "C" void kernel_launch(void* const* d_in, const int* in_sizes, int n_in,
                              void* d_out, int out_size)
{
    const float* Q = (const float*)d_in[0];
    const float* K = (const float*)d_in[1];
    const float* V = (const float*)d_in[2];
    // d_in[3] = attention_mask (all-ones, unused)
    // d_in[4] = sliding_window = 128 (hardcoded)

    const long long OUT_ELEMS = (long long)S_DIM * H_DIM * D_DIM;   // 3,145,728
    const long long W_ELEMS   = (long long)H_DIM * S_DIM * S_DIM;   // 201,326,592

    float* out = nullptr;
    float* w   = nullptr;
    const long long osz = (long long)out_size;
    if (osz == OUT_ELEMS) {
        out = (float*)d_out;
    } else if (osz == W_ELEMS) {
        w = (float*)d_out;
    } else {
        out = (float*)d_out;                 // tuple order: output, weights
        w   = (float*)d_out + OUT_ELEMS;
    }

    dim3 grid(2 * H_DIM * (S_DIM / TQ));     // 3072 blocks (parity-specialized)
    dim3 block(256);
    mb_attn_kernel<<<grid, block>>>(Q, K, V, out, w);
}

// round 14
// speedup vs baseline: 1.1573x; 1.0355x over previous
#include <cuda_runtime.h>
#include <cuda_bf16.h>

// ModernBertDecoderAttention: B=1, H=12, S=4096, D=64, fp32,
// causal + sliding_window=128.
// Outputs (tuple): attn_output [B,S,H,D], attn_weights [B,H,S,S].
//
// Grid-specialized single launch (3072 blocks):
//   odd blocks  -> zero-fill of out-of-band W spans via TMA BULK STORES
//                  (cp.async.bulk shared->global): one instruction per span,
//                  bypassing per-thread STG issue limits.
//   even blocks -> union-band QK + softmax; p staged shift-aligned in smem,
//                  reused for the W band-chunk writes (<=33 float4/row, __stcs)
//                  and the PV pass (aligned LDS.128).
// Band / out-of-band spans are exact complements -> each W element written once.

#define S_DIM 4096
#define H_DIM 12
#define D_DIM 64
#define SW    128
#define TQ    32
#define BAND  (TQ + SW - 1)   /* 159 */
#define UB    131             /* union band per warp: 128 + 3 */
#define KSTR  68              /* 68%32==4 -> conflict-free; 272B row, 16B aligned */
#define PQP   168             /* padded p slots per query (mult of 4; sh+159 < 168) */

__global__ __launch_bounds__(256, 4)
void mb_attn_kernel(const float* __restrict__ Q,
                    const float* __restrict__ K,
                    const float* __restrict__ V,
                    float* __restrict__ Out,   // [S,H,D] or nullptr
                    float* __restrict__ W)     // [H,S,S] or nullptr
{
    __shared__ __align__(16) float Ks[BAND * KSTR];   // 43,248 B (zeros / p stage)

    const int role = blockIdx.x & 1;
    const int idx  = blockIdx.x >> 1;           // 0..1535
    const int h    = idx / (S_DIM / TQ);
    const int i0   = (idx % (S_DIM / TQ)) * TQ;
    const int tid  = threadIdx.x;

    // ================= zero-fill blocks (odd): TMA bulk stores =================
    if (role) {
        if (!W) return;
        // zero 16 KB smem source buffer (max span = 16368 B)
        float4* zb = (float4*)Ks;
#pragma unroll
        for (int k = tid; k < 1024; k += 256)
            zb[k] = make_float4(0.f, 0.f, 0.f, 0.f);
        asm volatile("fence.proxy.async.shared::cta;" ::: "memory");
        __syncthreads();

        const unsigned saddr = (unsigned)__cvta_generic_to_shared(Ks);
        if (tid < 64) {
            const int r  = tid >> 1;            // row within tile
            const int sp = tid & 1;             // 0=prefix, 1=suffix
            const int i  = i0 + r;
            char* rowb = (char*)(W + ((size_t)h * S_DIM + i) * S_DIM);
            const int c0 = ((i > 127) ? (i - 127) : 0) >> 2;  // first band chunk
            const int c1 = i >> 2;                            // last band chunk
            long long off; int bytes;
            if (sp == 0) { off = 0;                         bytes = c0 * 16; }
            else         { off = (long long)(c1 + 1) * 16;  bytes = (1024 - (c1 + 1)) * 16; }
            if (bytes > 0) {
                asm volatile(
                    "cp.async.bulk.global.shared::cta.bulk_group [%0], [%1], %2;"
                    :: "l"(rowb + off), "r"(saddr), "r"(bytes) : "memory");
                asm volatile("cp.async.bulk.commit_group;" ::: "memory");
                asm volatile("cp.async.bulk.wait_group 0;" ::: "memory");
            }
        }
        return;
    }

    // ================= compute blocks (even) =================
    const int lane = tid & 31;
    const int w    = tid >> 5;                 // warp 0..7
    const int qb   = w * 4;                    // first query of this warp
    const int g0 = i0 - (SW - 1);              // global key row of smem row 0
    const int gq = g0 + qb;                    // global key row of union slot 0
    const int sh = gq & 3;                     // alignment shift (0..3)
    const int ga = gq - sh;                    // 4-aligned base key row

    // ---- stage K band into smem (coalesced float4, zero-fill for g<0) ----
    {
        const float4* K4 = (const float4*)(K + (size_t)h * S_DIM * D_DIM);
        for (int t = tid; t < BAND * (D_DIM / 4); t += 256) {
            const int row = t >> 4;
            const int c4  = t & 15;
            const int g   = g0 + row;
            float4 v = make_float4(0.f, 0.f, 0.f, 0.f);
            if (g >= 0) v = K4[(size_t)g * (D_DIM / 4) + c4];
            *(float4*)&Ks[row * KSTR + c4 * 4] = v;
        }
    }
    __syncthreads();

    // ---- QK: s[r][q] = q_q . k_(u=lane+32r), shared K loads across 4 q ----
    float s[5][4];
#pragma unroll
    for (int r = 0; r < 5; r++)
#pragma unroll
        for (int q = 0; q < 4; q++) s[r][q] = 0.f;

    {
        const float4* q4 =
            (const float4*)(Q + ((size_t)h * S_DIM + i0 + qb) * D_DIM);
#pragma unroll
        for (int d = 0; d < D_DIM / 4; d++) {
            const float4 q0 = __ldg(q4 + d);                    // broadcasts
            const float4 q1 = __ldg(q4 + 16 + d);
            const float4 q2 = __ldg(q4 + 32 + d);
            const float4 q3 = __ldg(q4 + 48 + d);
#pragma unroll
            for (int r = 0; r < 5; r++) {
                const int u   = lane + 32 * r;
                const int row = qb + ((u <= UB - 1) ? u : 0);   // clamp r=4 tail
                const float4 k = *(const float4*)&Ks[row * KSTR + 4 * d];
                s[r][0] = fmaf(q0.x, k.x, s[r][0]); s[r][0] = fmaf(q0.y, k.y, s[r][0]);
                s[r][0] = fmaf(q0.z, k.z, s[r][0]); s[r][0] = fmaf(q0.w, k.w, s[r][0]);
                s[r][1] = fmaf(q1.x, k.x, s[r][1]); s[r][1] = fmaf(q1.y, k.y, s[r][1]);
                s[r][1] = fmaf(q1.z, k.z, s[r][1]); s[r][1] = fmaf(q1.w, k.w, s[r][1]);
                s[r][2] = fmaf(q2.x, k.x, s[r][2]); s[r][2] = fmaf(q2.y, k.y, s[r][2]);
                s[r][2] = fmaf(q2.z, k.z, s[r][2]); s[r][2] = fmaf(q2.w, k.w, s[r][2]);
                s[r][3] = fmaf(q3.x, k.x, s[r][3]); s[r][3] = fmaf(q3.y, k.y, s[r][3]);
                s[r][3] = fmaf(q3.z, k.z, s[r][3]); s[r][3] = fmaf(q3.w, k.w, s[r][3]);
            }
        }
    }

    // ---- mask + softmax per query (warp shuffles); s becomes p ----
#pragma unroll
    for (int q = 0; q < 4; q++) {
        float mv = -1e30f;
#pragma unroll
        for (int r = 0; r < 5; r++) {
            const int u  = lane + 32 * r;
            const int tp = u - q;                       // band position
            const bool valid = (tp >= 0) && (tp <= 127) && (gq + u >= 0);
            const float sv = valid ? s[r][q] * 0.125f : -1e30f;
            s[r][q] = sv;
            mv = fmaxf(mv, sv);
        }
#pragma unroll
        for (int off = 16; off > 0; off >>= 1)
            mv = fmaxf(mv, __shfl_xor_sync(0xffffffffu, mv, off));
        float sum = 0.f;
#pragma unroll
        for (int r = 0; r < 5; r++) {
            const float e = __expf(s[r][q] - mv);       // ==0 for masked slots
            s[r][q] = e;
            sum += e;
        }
#pragma unroll
        for (int off = 16; off > 0; off >>= 1)
            sum += __shfl_xor_sync(0xffffffffu, sum, off);
        const float inv = 1.0f / sum;
#pragma unroll
        for (int r = 0; r < 5; r++) s[r][q] *= inv;
    }

    // ---- stage p in smem, shift-aligned: pw[q*PQP + sh + u] = p(q,u) ----
    __syncthreads();                            // all QK reads of Ks done
    float* pw = &Ks[w * (4 * PQP)];             // warp-private region
    {
        float4* pz = (float4*)pw;
#pragma unroll
        for (int k = lane; k < PQP; k += 32)    // zero 168 float4 (full region)
            pz[k] = make_float4(0.f, 0.f, 0.f, 0.f);
    }
    __syncwarp();
#pragma unroll
    for (int q = 0; q < 4; q++)
#pragma unroll
        for (int r = 0; r < 5; r++)
            pw[q * PQP + sh + lane + 32 * r] = s[r][q];   // masked -> 0
    __syncwarp();

    // ---- W band write: <=33 aligned float4 chunks per row (__stcs) ----
    if (W) {
        const int obase = ga >> 2;              // aligned base chunk (may be <0)
#pragma unroll
        for (int q = 0; q < 4; q++) {
            const int i  = i0 + qb + q;
            const int c0 = ((i > 127) ? (i - 127) : 0) >> 2;
            const int c1 = i >> 2;
            float4* wr4 = (float4*)(W + ((size_t)h * S_DIM + i) * S_DIM);
            const float4* pp4 = (const float4*)&pw[q * PQP];
            int c = c0 + lane;
            if (c <= c1) __stcs(&wr4[c], pp4[c - obase]);
            c += 32;
            if (c <= c1) __stcs(&wr4[c], pp4[c - obase]);
        }
    }

    // ---- PV: p via aligned LDS.128; V row shared by 4 queries ----
    if (Out) {
        float2 acc0 = make_float2(0.f, 0.f);
        float2 acc1 = make_float2(0.f, 0.f);
        float2 acc2 = make_float2(0.f, 0.f);
        float2 acc3 = make_float2(0.f, 0.f);
        const float*  vb = V + (size_t)h * S_DIM * D_DIM + 2 * lane;
        const float4* pb = (const float4*)pw;
#pragma unroll
        for (int xb = 0; xb < 34; xb++) {
            const float4 p0 = pb[xb];                    // q=0
            const float4 p1 = pb[(PQP / 4)     + xb];    // q=1
            const float4 p2 = pb[(PQP / 4) * 2 + xb];    // q=2
            const float4 p3 = pb[(PQP / 4) * 3 + xb];    // q=3
#pragma unroll
            for (int e = 0; e < 4; e++) {
                int j = ga + 4 * xb + e;
                if (j < 0) j = 0;                        // p==0 there
                if (j > S_DIM - 1) j = S_DIM - 1;        // p==0 there
                const float2 vv = *(const float2*)&vb[(size_t)j * D_DIM];
                const float f0 = (e == 0) ? p0.x : (e == 1) ? p0.y : (e == 2) ? p0.z : p0.w;
                const float f1 = (e == 0) ? p1.x : (e == 1) ? p1.y : (e == 2) ? p1.z : p1.w;
                const float f2 = (e == 0) ? p2.x : (e == 1) ? p2.y : (e == 2) ? p2.z : p2.w;
                const float f3 = (e == 0) ? p3.x : (e == 1) ? p3.y : (e == 2) ? p3.z : p3.w;
                acc0.x = fmaf(f0, vv.x, acc0.x); acc0.y = fmaf(f0, vv.y, acc0.y);
                acc1.x = fmaf(f1, vv.x, acc1.x); acc1.y = fmaf(f1, vv.y, acc1.y);
                acc2.x = fmaf(f2, vv.x, acc2.x); acc2.y = fmaf(f2, vv.y, acc2.y);
                acc3.x = fmaf(f3, vv.x, acc3.x); acc3.y = fmaf(f3, vv.y, acc3.y);
            }
        }
        const int ib = i0 + qb;
        __stcs((float2*)&Out[((size_t)(ib    ) * H_DIM + h) * D_DIM + 2 * lane], acc0);
        __stcs((float2*)&Out[((size_t)(ib + 1) * H_DIM + h) * D_DIM + 2 * lane], acc1);
        __stcs((float2*)&Out[((size_t)(ib + 2) * H_DIM + h) * D_DIM + 2 * lane], acc2);
        __stcs((float2*)&Out[((size_t)(ib + 3) * H_DIM + h) * D_DIM + 2 * lane], acc3);
    }
}

extern "C" void kernel_launch(void* const* d_in, const int* in_sizes, int n_in,
                              void* d_out, int out_size)
{
    const float* Q = (const float*)d_in[0];
    const float* K = (const float*)d_in[1];
    const float* V = (const float*)d_in[2];
    // d_in[3] = attention_mask (all-ones, unused)
    // d_in[4] = sliding_window = 128 (hardcoded)

    const long long OUT_ELEMS = (long long)S_DIM * H_DIM * D_DIM;   // 3,145,728
    const long long W_ELEMS   = (long long)H_DIM * S_DIM * S_DIM;   // 201,326,592

    float* out = nullptr;
    float* w   = nullptr;
    const long long osz = (long long)out_size;
    if (osz == OUT_ELEMS) {
        out = (float*)d_out;
    } else if (osz == W_ELEMS) {
        w = (float*)d_out;
    } else {
        out = (float*)d_out;                 // tuple order: output, weights
        w   = (float*)d_out + OUT_ELEMS;
    }

    dim3 grid(2 * H_DIM * (S_DIM / TQ));     // 3072 blocks (parity-specialized)
    dim3 block(256);
    mb_attn_kernel<<<grid, block>>>(Q, K, V, out, w);
}